// round 9
// baseline (speedup 1.0000x reference)
#include <cuda_runtime.h>
#include <math.h>

// ---------------------------------------------------------------------------
// GCN 2-layer forward:  out = log_softmax( A' relu(A' (x W1) + b1) W2 + b2 )
// A' = D^-1/2 (A + I) D^-1/2.
//
// R5: deterministic CSR-gather aggregation (NO float atomics — graph-replay
// validation rejects them), high-MLP gather kernels:
//   agg layer1: warp per (node, 32-col quarter), 8 gathers in flight
//   agg layer2: warp per node (float2/lane), fused log_softmax
// Launch order puts k_gemm<128> at 0-based index 3 (the ncu capture slot).
// g_cnt self-restores (zeroed inside k_scan1 after reading).
// ---------------------------------------------------------------------------

#define NMAX 100000
#define EMAX 1600000
#define SCAN_BS 512
#define MAX_SCAN_BLOCKS 256   // ceil(100000/512)=196 <= 256

__device__ int g_cnt[NMAX];          // zero-initialized at module load; self-restored
__device__ int g_rowoff[NMAX + 1];
__device__ int g_cursor[NMAX];
__device__ int g_blksums[MAX_SCAN_BLOCKS];
__device__ int g_csr[EMAX];
__device__ float g_dinv[NMAX];
__device__ __align__(16) float g_hs1[(size_t)NMAX * 128];  // dinv * (x W1)
__device__ __align__(16) float g_h2[(size_t)NMAX * 128];   // relu(agg1)
__device__ __align__(16) float g_zs[(size_t)NMAX * 64];    // dinv * (h2 W2)

// ---------------------------------------------------------------------------
// launch 0
__global__ void k_hist(const int* __restrict__ dst, int e) {
    int i = blockIdx.x * blockDim.x + threadIdx.x;
    if (i < e) atomicAdd(&g_cnt[dst[i]], 1);
}

// launch 1
__global__ void k_dinv(int n) {
    int i = blockIdx.x * blockDim.x + threadIdx.x;
    if (i < n) g_dinv[i] = rsqrtf((float)(g_cnt[i] + 1));  // +1 self loop
}

// launch 2: exclusive scan of g_cnt -> g_rowoff (block-local), partials out.
// Also zeroes g_cnt so the next kernel_launch call starts clean (invariant:
// g_cnt == 0 on entry; true at module load and restored every call).
__global__ void k_scan1(int n) {
    __shared__ int s[SCAN_BS];
    int t = threadIdx.x;
    int i = blockIdx.x * SCAN_BS + t;
    int v = (i < n) ? g_cnt[i] : 0;
    if (i < n) g_cnt[i] = 0;
    s[t] = v;
    __syncthreads();
#pragma unroll
    for (int off = 1; off < SCAN_BS; off <<= 1) {
        int x = 0;
        if (t >= off) x = s[t - off];
        __syncthreads();
        s[t] += x;
        __syncthreads();
    }
    if (i < n) g_rowoff[i] = s[t] - v;  // exclusive within block
    if (t == SCAN_BS - 1) g_blksums[blockIdx.x] = s[t];
}

// launch 4: exclusive scan of block sums (single block)
__global__ void k_scan2(int nb) {
    __shared__ int s[MAX_SCAN_BLOCKS];
    int t = threadIdx.x;
    int v = (t < nb) ? g_blksums[t] : 0;
    s[t] = v;
    __syncthreads();
#pragma unroll
    for (int off = 1; off < MAX_SCAN_BLOCKS; off <<= 1) {
        int x = 0;
        if (t >= off) x = s[t - off];
        __syncthreads();
        s[t] += x;
        __syncthreads();
    }
    if (t < nb) g_blksums[t] = s[t] - v;
}

// launch 5
__global__ void k_scan3(int n, int e) {
    int i = blockIdx.x * blockDim.x + threadIdx.x;
    if (i < n) {
        int r = g_rowoff[i] + g_blksums[i / SCAN_BS];
        g_rowoff[i] = r;
        g_cursor[i] = r;
    }
    if (i == 0) g_rowoff[n] = e;
}

// launch 6
__global__ void k_scatter(const int* __restrict__ src, const int* __restrict__ dst, int e) {
    int i = blockIdx.x * blockDim.x + threadIdx.x;
    if (i < e) {
        int d = dst[i];
        int p = atomicAdd(&g_cursor[d], 1);
        g_csr[p] = src[i];
    }
}

// ---------------------------------------------------------------------------
// GEMM: out[i][c] = dinv[i] * sum_k X[i][k] * W[k][c]   (K = 128 fixed)
// Block: 64 rows x NC cols, 256 threads, thread = 4 rows x NC/16 cols.
// launch 3 (NC=128) <- ncu capture slot
// ---------------------------------------------------------------------------
#define XS_STRIDE 129

template <int NC>
__global__ void k_gemm(const float* __restrict__ X, const float* __restrict__ W,
                       float* __restrict__ out, int n) {
    extern __shared__ float sm[];
    float* Ws = sm;                 // 128 * NC
    float* Xs = sm + 128 * NC;      // 64 * XS_STRIDE
    const int tid = threadIdx.x;
    const int row0 = blockIdx.x * 64;

    for (int i = tid; i < 128 * NC; i += 256) Ws[i] = W[i];
    for (int i = tid; i < 64 * 128; i += 256) {
        int r = i >> 7, c = i & 127;
        int gr = row0 + r;
        Xs[r * XS_STRIDE + c] = (gr < n) ? X[(size_t)gr * 128 + c] : 0.f;
    }
    __syncthreads();

    const int tr = tid >> 4;
    const int tc = tid & 15;
    constexpr int TN = NC / 16;
    float acc[4][TN];
#pragma unroll
    for (int r = 0; r < 4; r++)
#pragma unroll
        for (int j = 0; j < TN; j++) acc[r][j] = 0.f;

#pragma unroll 2
    for (int k = 0; k < 128; k++) {
        float xr[4];
#pragma unroll
        for (int r = 0; r < 4; r++) xr[r] = Xs[(tr * 4 + r) * XS_STRIDE + k];
#pragma unroll
        for (int j = 0; j < TN; j++) {
            float w = Ws[k * NC + tc + 16 * j];
#pragma unroll
            for (int r = 0; r < 4; r++) acc[r][j] = fmaf(xr[r], w, acc[r][j]);
        }
    }

#pragma unroll
    for (int r = 0; r < 4; r++) {
        int gr = row0 + tr * 4 + r;
        if (gr < n) {
            float dv = g_dinv[gr];
#pragma unroll
            for (int j = 0; j < TN; j++)
                out[(size_t)gr * NC + tc + 16 * j] = dv * acc[r][j];
        }
    }
}

// ---------------------------------------------------------------------------
// Layer-1 aggregation + relu. Warp per (node, 32-col quarter): 4n warps.
// Each neighbor gather = one 128B line; indices preloaded coalesced (32/warp)
// and shfl-broadcast; inner loop 8 gathers in flight.
//   h2[node,col] = relu( dinv*(hs[node,col] + sum_j hs[j,col]) + b[col] )
// ---------------------------------------------------------------------------
__global__ void k_agg_relu(const float* __restrict__ hs, const float* __restrict__ bias,
                           float* __restrict__ out, int n) {
    const int gw = (blockIdx.x * blockDim.x + threadIdx.x) >> 5;
    const int lane = threadIdx.x & 31;
    const int node = gw >> 2;
    if (node >= n) return;
    const int col = ((gw & 3) << 5) + lane;
    const float* __restrict__ hcol = hs + col;

    float acc = hcol[(size_t)node * 128];          // self loop
    const int p = g_rowoff[node];
    const int end = g_rowoff[node + 1];

    for (int base = p; base < end; base += 32) {
        const int nv = min(32, end - base);
        int idx = (base + lane < end) ? g_csr[base + lane] : 0;
        int m = 0;
        for (; m + 8 <= nv; m += 8) {
            int j0 = __shfl_sync(0xffffffffu, idx, m + 0);
            int j1 = __shfl_sync(0xffffffffu, idx, m + 1);
            int j2 = __shfl_sync(0xffffffffu, idx, m + 2);
            int j3 = __shfl_sync(0xffffffffu, idx, m + 3);
            int j4 = __shfl_sync(0xffffffffu, idx, m + 4);
            int j5 = __shfl_sync(0xffffffffu, idx, m + 5);
            int j6 = __shfl_sync(0xffffffffu, idx, m + 6);
            int j7 = __shfl_sync(0xffffffffu, idx, m + 7);
            float v0 = hcol[(size_t)j0 * 128];
            float v1 = hcol[(size_t)j1 * 128];
            float v2 = hcol[(size_t)j2 * 128];
            float v3 = hcol[(size_t)j3 * 128];
            float v4 = hcol[(size_t)j4 * 128];
            float v5 = hcol[(size_t)j5 * 128];
            float v6 = hcol[(size_t)j6 * 128];
            float v7 = hcol[(size_t)j7 * 128];
            acc += ((v0 + v1) + (v2 + v3)) + ((v4 + v5) + (v6 + v7));
        }
        for (; m < nv; m++) {
            int j = __shfl_sync(0xffffffffu, idx, m);
            acc += hcol[(size_t)j * 128];
        }
    }

    float r = fmaf(g_dinv[node], acc, bias[col]);
    out[(size_t)node * 128 + col] = fmaxf(r, 0.f);
}

// ---------------------------------------------------------------------------
// Layer-2 aggregation + log_softmax. Warp per node, float2 per lane (64 cols).
// Indices preloaded coalesced; inner loop 4 float2-gathers (8 lines) in flight.
// ---------------------------------------------------------------------------
__global__ void k_agg_softmax(const float* __restrict__ zs, const float* __restrict__ bias,
                              float* __restrict__ out, int n) {
    const int gw = (blockIdx.x * blockDim.x + threadIdx.x) >> 5;
    const int lane = threadIdx.x & 31;
    if (gw >= n) return;

    float2 acc = *(const float2*)(zs + (size_t)gw * 64 + lane * 2);  // self loop
    const int p = g_rowoff[gw];
    const int end = g_rowoff[gw + 1];

    for (int base = p; base < end; base += 32) {
        const int nv = min(32, end - base);
        int idx = (base + lane < end) ? g_csr[base + lane] : 0;
        int m = 0;
        for (; m + 4 <= nv; m += 4) {
            int j0 = __shfl_sync(0xffffffffu, idx, m + 0);
            int j1 = __shfl_sync(0xffffffffu, idx, m + 1);
            int j2 = __shfl_sync(0xffffffffu, idx, m + 2);
            int j3 = __shfl_sync(0xffffffffu, idx, m + 3);
            float2 v0 = *(const float2*)(zs + (size_t)j0 * 64 + lane * 2);
            float2 v1 = *(const float2*)(zs + (size_t)j1 * 64 + lane * 2);
            float2 v2 = *(const float2*)(zs + (size_t)j2 * 64 + lane * 2);
            float2 v3 = *(const float2*)(zs + (size_t)j3 * 64 + lane * 2);
            acc.x += (v0.x + v1.x) + (v2.x + v3.x);
            acc.y += (v0.y + v1.y) + (v2.y + v3.y);
        }
        for (; m < nv; m++) {
            int j = __shfl_sync(0xffffffffu, idx, m);
            float2 v = *(const float2*)(zs + (size_t)j * 64 + lane * 2);
            acc.x += v.x; acc.y += v.y;
        }
    }

    float dv = g_dinv[gw];
    float2 b = *(const float2*)(bias + lane * 2);
    float o0 = fmaf(dv, acc.x, b.x);
    float o1 = fmaf(dv, acc.y, b.y);

    // log_softmax over 64 values held 2-per-lane
    float mx = fmaxf(o0, o1);
#pragma unroll
    for (int off = 16; off; off >>= 1) mx = fmaxf(mx, __shfl_xor_sync(0xffffffffu, mx, off));
    float ss = expf(o0 - mx) + expf(o1 - mx);
#pragma unroll
    for (int off = 16; off; off >>= 1) ss += __shfl_xor_sync(0xffffffffu, ss, off);
    float lse = mx + logf(ss);

    float2 o; o.x = o0 - lse; o.y = o1 - lse;
    *(float2*)(out + (size_t)gw * 64 + lane * 2) = o;
}

// ---------------------------------------------------------------------------
extern "C" void kernel_launch(void* const* d_in, const int* in_sizes, int n_in,
                              void* d_out, int out_size) {
    const float* x  = (const float*)d_in[0];
    const int*   ei = (const int*)d_in[1];
    const float* W1 = (const float*)d_in[2];
    const float* b1 = (const float*)d_in[3];
    const float* W2 = (const float*)d_in[4];
    const float* b2 = (const float*)d_in[5];
    float* out = (float*)d_out;

    const int n = in_sizes[0] / 128;
    const int e = in_sizes[1] / 2;
    const int* src = ei;
    const int* dst = ei + e;

    const int TB = 256;
    const int gN = (n + TB - 1) / TB;
    const int gE = (e + TB - 1) / TB;
    const int nb = (n + SCAN_BS - 1) / SCAN_BS;
    const int gG = (n + 63) / 64;
    const int gA1 = (n * 128 + TB - 1) / TB;  // 4n warps (node-quarter)
    const int gA2 = (n * 32 + TB - 1) / TB;   // n warps

    const int SM1 = (128 * 128 + 64 * XS_STRIDE) * 4;
    const int SM2 = (128 * 64 + 64 * XS_STRIDE) * 4;
    cudaFuncSetAttribute(k_gemm<128>, cudaFuncAttributeMaxDynamicSharedMemorySize, SM1);
    cudaFuncSetAttribute(k_gemm<64>,  cudaFuncAttributeMaxDynamicSharedMemorySize, SM2);

    k_hist<<<gE, TB>>>(dst, e);                              // 0
    k_dinv<<<gN, TB>>>(n);                                   // 1
    k_scan1<<<nb, SCAN_BS>>>(n);                             // 2  (+ restores g_cnt=0)
    k_gemm<128><<<gG, 256, SM1>>>(x, W1, g_hs1, n);          // 3  <- ncu capture slot
    k_scan2<<<1, MAX_SCAN_BLOCKS>>>(nb);                     // 4
    k_scan3<<<gN, TB>>>(n, e);                               // 5
    k_scatter<<<gE, TB>>>(src, dst, e);                      // 6
    k_agg_relu<<<gA1, TB>>>(g_hs1, b1, g_h2, n);             // 7
    k_gemm<64><<<gG, 256, SM2>>>(g_h2, W2, g_zs, n);         // 8
    k_agg_softmax<<<gA2, TB>>>(g_zs, b2, out, n);            // 9
}

// round 10
// speedup vs baseline: 2.1468x; 2.1468x over previous
#include <cuda_runtime.h>
#include <math.h>

// ---------------------------------------------------------------------------
// GCN 2-layer forward:  out = log_softmax( A' relu(A' (x W1) + b1) W2 + b2 )
// A' = D^-1/2 (A + I) D^-1/2.
//
// R9 layout:
//   0 k_hist        degree histogram (int atomics)
//   1 k_scan_fused  single-block scan: rowoff/cursor/dinv, restores g_cnt=0
//   2 k_scatter     CSR fill (counting sort)
//   3 k_agg1        layer-1 aggregation on x (aggregate-first!)  <- ncu slot
//   4 k_gemm<128,1> h2 = relu(ax W1 + b1)
//   5 k_gemm<64,0>  zs = dinv * (h2 W2)
//   6 k_agg_softmax out = log_softmax(dinv*(sum zs) + b2)
// ---------------------------------------------------------------------------

#define NMAX 100000
#define EMAX 1600000

__device__ int g_cnt[NMAX];          // zero at module load; self-restored each call
__device__ int g_rowoff[NMAX + 1];
__device__ int g_cursor[NMAX];
__device__ float g_dinv[NMAX];
__device__ int g_csr[EMAX];
__device__ __align__(16) float g_ax[(size_t)NMAX * 128];  // dinv_i*(sum dinv_j x_j + dinv_i x_i)
__device__ __align__(16) float g_h2[(size_t)NMAX * 128];
__device__ __align__(16) float g_zs[(size_t)NMAX * 64];

// ---------------------------------------------------------------------------
__global__ void k_hist(const int* __restrict__ dst, int e) {
    int i = blockIdx.x * blockDim.x + threadIdx.x;
    if (i < e) atomicAdd(&g_cnt[dst[i]], 1);
}

// Single-block fused: exclusive scan of g_cnt -> g_rowoff & g_cursor,
// dinv = rsqrt(cnt+1), and zero g_cnt (restore invariant for next call).
__global__ void k_scan_fused(int n, int e) {
    __shared__ int warp_sums[32];
    __shared__ int s_base;
    const int t = threadIdx.x;
    const int lane = t & 31, wid = t >> 5;
    if (t == 0) s_base = 0;
    __syncthreads();

    for (int start = 0; start < n; start += 1024) {
        int i = start + t;
        int v = (i < n) ? g_cnt[i] : 0;

        // inclusive warp scan
        int sc = v;
#pragma unroll
        for (int o = 1; o < 32; o <<= 1) {
            int u = __shfl_up_sync(0xffffffffu, sc, o);
            if (lane >= o) sc += u;
        }
        if (lane == 31) warp_sums[wid] = sc;
        __syncthreads();
        if (wid == 0) {
            int ws = warp_sums[lane];
#pragma unroll
            for (int o = 1; o < 32; o <<= 1) {
                int u = __shfl_up_sync(0xffffffffu, ws, o);
                if (lane >= o) ws += u;
            }
            warp_sums[lane] = ws;  // inclusive over warp totals
        }
        __syncthreads();

        int excl = sc - v + (wid ? warp_sums[wid - 1] : 0) + s_base;
        if (i < n) {
            g_rowoff[i] = excl;
            g_cursor[i] = excl;
            g_dinv[i] = rsqrtf((float)(v + 1));  // +1 self loop
            g_cnt[i] = 0;
        }
        __syncthreads();                       // all reads of s_base done
        if (t == 0) s_base += warp_sums[31];   // chunk total
        __syncthreads();
    }
    if (t == 0) g_rowoff[n] = e;
}

__global__ void k_scatter(const int* __restrict__ src, const int* __restrict__ dst, int e) {
    int i = blockIdx.x * blockDim.x + threadIdx.x;
    if (i < e) {
        int d = dst[i];
        int p = atomicAdd(&g_cursor[d], 1);
        g_csr[p] = src[i];
    }
}

// ---------------------------------------------------------------------------
// Layer-1 aggregation on raw input x (aggregate-first).
// Block = 128 threads = one node, thread t = column t.
//   ax[i,t] = dinv_i * ( dinv_i * x[i,t] + sum_j dinv_j * x[j,t] )
// Indices + dinv[j] staged in smem per 128-chunk; inner loop 8-wide so 8
// independent coalesced 512B row loads are in flight per warp at all times.
// ---------------------------------------------------------------------------
#define AGG_CH 128

__global__ void k_agg1(const float* __restrict__ x, float* __restrict__ out, int n) {
    __shared__ int s_idx[AGG_CH];
    __shared__ float s_d[AGG_CH];
    const int node = blockIdx.x;
    const int t = threadIdx.x;  // column
    const float* __restrict__ xc = x + t;

    const float di = g_dinv[node];
    float acc = di * xc[(size_t)node * 128];  // self loop (dinv_i * x_i)

    const int p = g_rowoff[node];
    const int end = g_rowoff[node + 1];

    for (int base = p; base < end; base += AGG_CH) {
        const int nv = min(AGG_CH, end - base);
        __syncthreads();
        if (t < nv) {
            int j = g_csr[base + t];
            s_idx[t] = j;
            s_d[t] = g_dinv[j];
        }
        __syncthreads();
        int m = 0;
        for (; m + 8 <= nv; m += 8) {
            int j0 = s_idx[m + 0], j1 = s_idx[m + 1], j2 = s_idx[m + 2], j3 = s_idx[m + 3];
            int j4 = s_idx[m + 4], j5 = s_idx[m + 5], j6 = s_idx[m + 6], j7 = s_idx[m + 7];
            float d0 = s_d[m + 0], d1 = s_d[m + 1], d2 = s_d[m + 2], d3 = s_d[m + 3];
            float d4 = s_d[m + 4], d5 = s_d[m + 5], d6 = s_d[m + 6], d7 = s_d[m + 7];
            float v0 = xc[(size_t)j0 * 128];
            float v1 = xc[(size_t)j1 * 128];
            float v2 = xc[(size_t)j2 * 128];
            float v3 = xc[(size_t)j3 * 128];
            float v4 = xc[(size_t)j4 * 128];
            float v5 = xc[(size_t)j5 * 128];
            float v6 = xc[(size_t)j6 * 128];
            float v7 = xc[(size_t)j7 * 128];
            acc = fmaf(d0, v0, acc); acc = fmaf(d1, v1, acc);
            acc = fmaf(d2, v2, acc); acc = fmaf(d3, v3, acc);
            acc = fmaf(d4, v4, acc); acc = fmaf(d5, v5, acc);
            acc = fmaf(d6, v6, acc); acc = fmaf(d7, v7, acc);
        }
        for (; m < nv; m++)
            acc = fmaf(s_d[m], xc[(size_t)s_idx[m] * 128], acc);
    }

    out[(size_t)node * 128 + t] = di * acc;
}

// ---------------------------------------------------------------------------
// GEMM: acc[i][c] = sum_k X[i][k] * W[k][c]   (K = 128 fixed)
// EPI 0: out = dinv[i]*acc            (layer-2 z, prescaled rows)
// EPI 1: out = relu(acc + bias[c])    (layer-1 h2; dinv already in g_ax)
// Block: 64 rows x NC cols, 256 threads, thread = 4 rows x NC/16 cols.
// ---------------------------------------------------------------------------
#define XS_STRIDE 129

template <int NC, int EPI>
__global__ void k_gemm(const float* __restrict__ X, const float* __restrict__ W,
                       const float* __restrict__ bias, float* __restrict__ out, int n) {
    extern __shared__ float sm[];
    float* Ws = sm;                 // 128 * NC
    float* Xs = sm + 128 * NC;      // 64 * XS_STRIDE
    const int tid = threadIdx.x;
    const int row0 = blockIdx.x * 64;

    for (int i = tid; i < 128 * NC; i += 256) Ws[i] = W[i];
    for (int i = tid; i < 64 * 128; i += 256) {
        int r = i >> 7, c = i & 127;
        int gr = row0 + r;
        Xs[r * XS_STRIDE + c] = (gr < n) ? X[(size_t)gr * 128 + c] : 0.f;
    }
    __syncthreads();

    const int tr = tid >> 4;
    const int tc = tid & 15;
    constexpr int TN = NC / 16;
    float acc[4][TN];
#pragma unroll
    for (int r = 0; r < 4; r++)
#pragma unroll
        for (int j = 0; j < TN; j++) acc[r][j] = 0.f;

#pragma unroll 2
    for (int k = 0; k < 128; k++) {
        float xr[4];
#pragma unroll
        for (int r = 0; r < 4; r++) xr[r] = Xs[(tr * 4 + r) * XS_STRIDE + k];
#pragma unroll
        for (int j = 0; j < TN; j++) {
            float w = Ws[k * NC + tc + 16 * j];
#pragma unroll
            for (int r = 0; r < 4; r++) acc[r][j] = fmaf(xr[r], w, acc[r][j]);
        }
    }

#pragma unroll
    for (int r = 0; r < 4; r++) {
        int gr = row0 + tr * 4 + r;
        if (gr < n) {
            if (EPI == 0) {
                float dv = g_dinv[gr];
#pragma unroll
                for (int j = 0; j < TN; j++)
                    out[(size_t)gr * NC + tc + 16 * j] = dv * acc[r][j];
            } else {
#pragma unroll
                for (int j = 0; j < TN; j++) {
                    float v = acc[r][j] + bias[tc + 16 * j];
                    out[(size_t)gr * NC + tc + 16 * j] = fmaxf(v, 0.f);
                }
            }
        }
    }
}

// ---------------------------------------------------------------------------
// Layer-2 aggregation + log_softmax. Warp per node, float2 per lane (64 cols).
// zs rows are prescaled by dinv_j. 8 gathers (16 lines) in flight.
// ---------------------------------------------------------------------------
__global__ void k_agg_softmax(const float* __restrict__ zs, const float* __restrict__ bias,
                              float* __restrict__ out, int n) {
    const int gw = (blockIdx.x * blockDim.x + threadIdx.x) >> 5;
    const int lane = threadIdx.x & 31;
    if (gw >= n) return;

    float2 acc = *(const float2*)(zs + (size_t)gw * 64 + lane * 2);  // self loop
    const int p = g_rowoff[gw];
    const int end = g_rowoff[gw + 1];

    for (int base = p; base < end; base += 32) {
        const int nv = min(32, end - base);
        int idx = (base + lane < end) ? g_csr[base + lane] : 0;
        int m = 0;
        for (; m + 8 <= nv; m += 8) {
            int j0 = __shfl_sync(0xffffffffu, idx, m + 0);
            int j1 = __shfl_sync(0xffffffffu, idx, m + 1);
            int j2 = __shfl_sync(0xffffffffu, idx, m + 2);
            int j3 = __shfl_sync(0xffffffffu, idx, m + 3);
            int j4 = __shfl_sync(0xffffffffu, idx, m + 4);
            int j5 = __shfl_sync(0xffffffffu, idx, m + 5);
            int j6 = __shfl_sync(0xffffffffu, idx, m + 6);
            int j7 = __shfl_sync(0xffffffffu, idx, m + 7);
            float2 v0 = *(const float2*)(zs + (size_t)j0 * 64 + lane * 2);
            float2 v1 = *(const float2*)(zs + (size_t)j1 * 64 + lane * 2);
            float2 v2 = *(const float2*)(zs + (size_t)j2 * 64 + lane * 2);
            float2 v3 = *(const float2*)(zs + (size_t)j3 * 64 + lane * 2);
            float2 v4 = *(const float2*)(zs + (size_t)j4 * 64 + lane * 2);
            float2 v5 = *(const float2*)(zs + (size_t)j5 * 64 + lane * 2);
            float2 v6 = *(const float2*)(zs + (size_t)j6 * 64 + lane * 2);
            float2 v7 = *(const float2*)(zs + (size_t)j7 * 64 + lane * 2);
            acc.x += ((v0.x + v1.x) + (v2.x + v3.x)) + ((v4.x + v5.x) + (v6.x + v7.x));
            acc.y += ((v0.y + v1.y) + (v2.y + v3.y)) + ((v4.y + v5.y) + (v6.y + v7.y));
        }
        for (; m < nv; m++) {
            int j = __shfl_sync(0xffffffffu, idx, m);
            float2 v = *(const float2*)(zs + (size_t)j * 64 + lane * 2);
            acc.x += v.x; acc.y += v.y;
        }
    }

    float dv = g_dinv[gw];
    float2 b = *(const float2*)(bias + lane * 2);
    float o0 = fmaf(dv, acc.x, b.x);
    float o1 = fmaf(dv, acc.y, b.y);

    float mx = fmaxf(o0, o1);
#pragma unroll
    for (int off = 16; off; off >>= 1) mx = fmaxf(mx, __shfl_xor_sync(0xffffffffu, mx, off));
    float ss = expf(o0 - mx) + expf(o1 - mx);
#pragma unroll
    for (int off = 16; off; off >>= 1) ss += __shfl_xor_sync(0xffffffffu, ss, off);
    float lse = mx + logf(ss);

    float2 o; o.x = o0 - lse; o.y = o1 - lse;
    *(float2*)(out + (size_t)gw * 64 + lane * 2) = o;
}

// ---------------------------------------------------------------------------
extern "C" void kernel_launch(void* const* d_in, const int* in_sizes, int n_in,
                              void* d_out, int out_size) {
    const float* x  = (const float*)d_in[0];
    const int*   ei = (const int*)d_in[1];
    const float* W1 = (const float*)d_in[2];
    const float* b1 = (const float*)d_in[3];
    const float* W2 = (const float*)d_in[4];
    const float* b2 = (const float*)d_in[5];
    float* out = (float*)d_out;

    const int n = in_sizes[0] / 128;
    const int e = in_sizes[1] / 2;
    const int* src = ei;
    const int* dst = ei + e;

    const int TB = 256;
    const int gE = (e + TB - 1) / TB;
    const int gG = (n + 63) / 64;
    const int gA2 = (n * 32 + TB - 1) / TB;   // warp per node

    const int SM1 = (128 * 128 + 64 * XS_STRIDE) * 4;
    const int SM2 = (128 * 64 + 64 * XS_STRIDE) * 4;
    cudaFuncSetAttribute((const void*)k_gemm<128, 1>, cudaFuncAttributeMaxDynamicSharedMemorySize, SM1);
    cudaFuncSetAttribute((const void*)k_gemm<64, 0>,  cudaFuncAttributeMaxDynamicSharedMemorySize, SM2);

    k_hist<<<gE, TB>>>(dst, e);                                  // 0
    k_scan_fused<<<1, 1024>>>(n, e);                             // 1 (dinv, rowoff, cursor, cnt=0)
    k_scatter<<<gE, TB>>>(src, dst, e);                          // 2
    k_agg1<<<n, 128>>>(x, g_ax, n);                              // 3  <- ncu capture slot
    k_gemm<128, 1><<<gG, 256, SM1>>>(g_ax, W1, b1, g_h2, n);     // 4
    k_gemm<64, 0><<<gG, 256, SM2>>>(g_h2, W2, nullptr, g_zs, n); // 5
    k_agg_softmax<<<gA2, TB>>>(g_zs, b2, out, n);                // 6
}